// round 1
// baseline (speedup 1.0000x reference)
#include <cuda_runtime.h>
#include <math.h>
#include <stdint.h>

// ---------------- problem constants ----------------
#define BB 256
#define HWD 196      // 14*14
#define CD 512
#define TS_INV (1.0f/0.03f)
#define TC_INV (1.0f/0.07f)

// ---------------- scratch (device globals; no runtime allocation) ----------------
__device__ float d_hfc[BB*CD];
__device__ float d_fa[BB*CD];
__device__ float d_faT[CD*BB];
__device__ float d_h1[BB*CD*HWD];     // relu(conv1) 102.8 MB
__device__ float d_fv[BB*CD*HWD];     // conv2 output 102.8 MB
__device__ float d_ind[BB*CD];
__device__ float d_ivn[BB*CD];
__device__ float d_ivnT[CD*BB];
__device__ float d_invrho[BB*HWD];
__device__ float d_Sij[BB*BB*HWD];    // 51.4 MB
__device__ float d_SP[BB*BB];
__device__ float d_SN[BB*BB];
__device__ float d_E[BB*BB];
__device__ float d_l1[BB];
__device__ float d_l2[BB];

// ---------------- reduction helpers ----------------
__device__ __forceinline__ float warpReduceSum(float v) {
#pragma unroll
    for (int o = 16; o > 0; o >>= 1) v += __shfl_xor_sync(0xffffffffu, v, o);
    return v;
}
__device__ __forceinline__ float warpReduceMax(float v) {
#pragma unroll
    for (int o = 16; o > 0; o >>= 1) v = fmaxf(v, __shfl_xor_sync(0xffffffffu, v, o));
    return v;
}
// requires blockDim.x multiple of 32
__device__ __forceinline__ float blockReduceSum(float v, float* red) {
    __syncthreads();
    int lane = threadIdx.x & 31, wid = threadIdx.x >> 5;
    v = warpReduceSum(v);
    if (lane == 0) red[wid] = v;
    __syncthreads();
    int nw = (blockDim.x + 31) >> 5;
    if (wid == 0) {
        float r = (threadIdx.x < nw) ? red[threadIdx.x] : 0.f;
        r = warpReduceSum(r);
        if (lane == 0) red[0] = r;
    }
    __syncthreads();
    return red[0];
}
__device__ __forceinline__ float blockReduceMax(float v, float* red) {
    __syncthreads();
    int lane = threadIdx.x & 31, wid = threadIdx.x >> 5;
    v = warpReduceMax(v);
    if (lane == 0) red[wid] = v;
    __syncthreads();
    int nw = (blockDim.x + 31) >> 5;
    if (wid == 0) {
        float r = (threadIdx.x < nw) ? red[threadIdx.x] : -INFINITY;
        r = warpReduceMax(r);
        if (lane == 0) red[0] = r;
    }
    __syncthreads();
    return red[0];
}

__device__ __forceinline__ float sigmoidf_stable(float x) {
    if (x >= 0.f) { float e = expf(-x); return 1.f / (1.f + e); }
    float e = expf(x); return e / (1.f + e);
}

// ---------------- GEMM: C[m,n] = sum_k A[m,k] * W[n,k], optional relu ----------------
// grid (N/16, M/16), block (16,16); K multiple of 16
__global__ void gemm_nt(const float* __restrict__ A, const float* __restrict__ W,
                        float* __restrict__ C, int K, int N, int relu) {
    __shared__ float As[16][17], Ws[16][17];
    int tx = threadIdx.x, ty = threadIdx.y;
    int m = blockIdx.y * 16 + ty;
    int n0 = blockIdx.x * 16;
    float acc = 0.f;
    for (int k0 = 0; k0 < K; k0 += 16) {
        As[ty][tx] = A[m * K + k0 + tx];
        Ws[ty][tx] = W[(n0 + ty) * K + k0 + tx];
        __syncthreads();
#pragma unroll
        for (int kk = 0; kk < 16; kk++) acc = fmaf(As[ty][kk], Ws[tx][kk], acc);
        __syncthreads();
    }
    C[m * N + n0 + tx] = relu ? fmaxf(acc, 0.f) : acc;
}

// ---------------- 3x3 SAME conv, NCHW, 14x14 ----------------
// block: 196 threads (one per spatial position); grid (OC/16, B)
// each thread accumulates 16 output channels; 4 input planes staged in SMEM
template<int IC, bool RELU>
__global__ void __launch_bounds__(196) conv3x3(const float* __restrict__ in,
                                               const float* __restrict__ w,
                                               float* __restrict__ out) {
    const int b = blockIdx.y;
    const int oc0 = blockIdx.x * 16;
    const int tid = threadIdx.x;              // 0..195
    __shared__ float plane[4][256];           // 16x16 padded planes
    __shared__ float wsh[4][9][16];           // [sub-ic][tap][oc]  (float4-readable)

#pragma unroll
    for (int s = 0; s < 4; s++)
        for (int t = tid; t < 256; t += 196) plane[s][t] = 0.f;

    float acc[16];
#pragma unroll
    for (int o = 0; o < 16; o++) acc[o] = 0.f;

    const int y = tid / 14, x = tid % 14;
    const float* inb = in + (size_t)b * IC * HWD;

    for (int ic0 = 0; ic0 < IC; ic0 += 4) {
        __syncthreads();
#pragma unroll
        for (int s = 0; s < 4; s++)
            plane[s][(y + 1) * 16 + (x + 1)] = inb[(ic0 + s) * HWD + tid];
        for (int e = tid; e < 576; e += 196) {
            int s = e / 144, r = e % 144;
            int t = r / 16, o = r % 16;
            wsh[s][t][o] = w[(((size_t)(oc0 + o)) * IC + ic0 + s) * 9 + t];
        }
        __syncthreads();
#pragma unroll
        for (int s = 0; s < 4; s++) {
            float v[9];
#pragma unroll
            for (int dy = 0; dy < 3; dy++)
#pragma unroll
                for (int dx = 0; dx < 3; dx++)
                    v[dy * 3 + dx] = plane[s][(y + dy) * 16 + (x + dx)];
#pragma unroll
            for (int t = 0; t < 9; t++) {
#pragma unroll
                for (int g = 0; g < 4; g++) {
                    const float4 w4 = *(const float4*)&wsh[s][t][g * 4];  // broadcast LDS.128
                    acc[g * 4 + 0] = fmaf(w4.x, v[t], acc[g * 4 + 0]);
                    acc[g * 4 + 1] = fmaf(w4.y, v[t], acc[g * 4 + 1]);
                    acc[g * 4 + 2] = fmaf(w4.z, v[t], acc[g * 4 + 2]);
                    acc[g * 4 + 3] = fmaf(w4.w, v[t], acc[g * 4 + 3]);
                }
            }
        }
    }
    float* ob = out + ((size_t)b * CD + oc0) * HWD + tid;
#pragma unroll
    for (int o = 0; o < 16; o++) {
        float r = acc[o];
        if (RELU) r = fmaxf(r, 0.f);
        ob[o * HWD] = r;
    }
}

// ---------------- masked mean pooling -> ind_vec ----------------
// block per b, 256 threads
__global__ void indvec_kernel(const float* __restrict__ fv, const int* __restrict__ masks,
                              float* __restrict__ ind) {
    int b = blockIdx.x;
    int tid = threadIdx.x;
    __shared__ float m_s[HWD];
    __shared__ float red[8];
    float mv = 0.f;
    if (tid < HWD) { mv = (float)masks[b * HWD + tid]; m_s[tid] = mv; }
    float tot = blockReduceSum(mv, red);
    float inv_m = 1.f / tot;
    int lane = tid & 31, wid = tid >> 5;
    for (int c = wid; c < CD; c += 8) {
        const float* rowp = fv + ((size_t)b * CD + c) * HWD;
        float s = 0.f;
        for (int p = lane; p < HWD; p += 32) s += rowp[p] * m_s[p];
        s = warpReduceSum(s);
        if (lane == 0) ind[b * CD + c] = s * inv_m;
    }
}

// ---------------- per (b,p) inverse channel L2 norm ----------------
// block per b, 196 threads
__global__ void invrho_kernel(const float* __restrict__ fv, float* __restrict__ invrho) {
    int b = blockIdx.x;
    int p = threadIdx.x;
    const float* base = fv + (size_t)b * CD * HWD + p;
    float s = 0.f;
    for (int c = 0; c < CD; c++) { float v = base[c * HWD]; s = fmaf(v, v, s); }
    invrho[b * HWD + p] = 1.f / fmaxf(sqrtf(s), 1e-12f);
}

// ---------------- normalize ind_vec -> ivn (+ transposed copy) ----------------
// block per b, 512 threads
__global__ void ivn_kernel(const float* __restrict__ ind, float* __restrict__ ivn,
                           float* __restrict__ ivnT) {
    int b = blockIdx.x, c = threadIdx.x;
    __shared__ float red[16];
    float v = ind[b * CD + c];
    float ss = blockReduceSum(v * v, red);
    float o = v / fmaxf(sqrtf(ss), 1e-12f);
    ivn[b * CD + c] = o;
    ivnT[c * BB + b] = o;
}

// ---------------- transpose fa ----------------
__global__ void transpose_fa(const float* __restrict__ fa, float* __restrict__ faT) {
    int idx = blockIdx.x * 256 + threadIdx.x;
    int b = idx >> 9, c = idx & 511;
    faT[c * BB + b] = fa[idx];
}

// ---------------- Sij[i,j,p] = <ivn[j], fv[i,:,p]> * invrho[i,p] ----------------
// grid (4 p-tiles, 4 j-tiles, 256 i), block (16,16), each thread 4x4 outputs
__global__ void sij_gemm(const float* __restrict__ ivn, const float* __restrict__ fv,
                         const float* __restrict__ invrho, float* __restrict__ Sij) {
    int i = blockIdx.z;
    int p0 = blockIdx.x * 64;
    int j0 = blockIdx.y * 64;
    __shared__ float As[64][17];
    __shared__ float Bs[16][65];
    int tid = threadIdx.y * 16 + threadIdx.x;
    float acc[4][4] = {};
    const float* fvi = fv + (size_t)i * CD * HWD;
    for (int k0 = 0; k0 < CD; k0 += 16) {
#pragma unroll
        for (int r = 0; r < 4; r++) {
            int e = tid + r * 256;
            int row = e >> 4, col = e & 15;
            As[row][col] = ivn[(j0 + row) * CD + k0 + col];
        }
#pragma unroll
        for (int r = 0; r < 4; r++) {
            int e = tid + r * 256;
            int row = e >> 6, col = e & 63;
            int p = p0 + col;
            Bs[row][col] = (p < HWD) ? fvi[(k0 + row) * HWD + p] : 0.f;
        }
        __syncthreads();
#pragma unroll
        for (int kk = 0; kk < 16; kk++) {
            float a[4], bb[4];
#pragma unroll
            for (int r = 0; r < 4; r++) a[r] = As[threadIdx.y * 4 + r][kk];
#pragma unroll
            for (int c = 0; c < 4; c++) bb[c] = Bs[kk][threadIdx.x * 4 + c];
#pragma unroll
            for (int r = 0; r < 4; r++)
#pragma unroll
                for (int c = 0; c < 4; c++)
                    acc[r][c] = fmaf(a[r], bb[c], acc[r][c]);
        }
        __syncthreads();
    }
#pragma unroll
    for (int r = 0; r < 4; r++) {
        int j = j0 + threadIdx.y * 4 + r;
#pragma unroll
        for (int c = 0; c < 4; c++) {
            int p = p0 + threadIdx.x * 4 + c;
            if (p < HWD)
                Sij[((size_t)(i * BB + j)) * HWD + p] = acc[r][c] * invrho[i * HWD + p];
        }
    }
}

// ---------------- exact top-k thresholds via bitonic sort + soft-mask pooling ----------------
// grid (256 j, 256 i), block 256
__global__ void topk_sp_sn(const float* __restrict__ Sij, float* __restrict__ SP,
                           float* __restrict__ SN) {
    int i = blockIdx.y, j = blockIdx.x;
    int tid = threadIdx.x;
    __shared__ float sm[256];
    __shared__ float red[8];
    const float* row = Sij + ((size_t)(i * BB + j)) * HWD;
    sm[tid] = (tid < HWD) ? row[tid] : -INFINITY;   // 60 pads sort to the bottom
    __syncthreads();
    // ascending bitonic sort of 256 elements
    for (int k = 2; k <= 256; k <<= 1) {
        for (int s = k >> 1; s > 0; s >>= 1) {
            int ixj = tid ^ s;
            if (ixj > tid) {
                float a = sm[tid], b2 = sm[ixj];
                bool up = ((tid & k) == 0);
                if ((a > b2) == up) { sm[tid] = b2; sm[ixj] = a; }
            }
            __syncthreads();
        }
    }
    // kth largest (k=19): idx 255-18 = 237 ; 98th smallest: idx 60+97 = 157
    float pos_thr = sm[237];
    float neg_thr = sm[157];
    float val = (tid >= 60) ? sm[tid] : 0.f;
    float mp = 0.f, mn = 0.f;
    if (tid >= 60) {
        mp = sigmoidf_stable((val - pos_thr) * TS_INV);
        mn = 1.f - sigmoidf_stable((val - neg_thr) * TS_INV);
    }
    float s_vp = blockReduceSum(val * mp, red);
    float s_p  = blockReduceSum(mp, red);
    float s_vn = blockReduceSum(val * mn, red);
    float s_n  = blockReduceSum(mn, red);
    if (tid == 0) {
        SP[i * BB + j] = s_vp / s_p;
        SN[i * BB + j] = s_vn / s_n;
    }
}

// ---------------- contrastive losses ----------------
// block per i, 256 threads (thread = j)
__global__ void loss12_kernel(const float* __restrict__ SP, const float* __restrict__ SN,
                              float* __restrict__ l1, float* __restrict__ l2) {
    int i = blockIdx.x, j = threadIdx.x;
    __shared__ float red[8];
    float a1 = SP[i * BB + j] * TC_INV, a2 = SN[i * BB + j] * TC_INV;
    float b1 = SP[j * BB + i] * TC_INV, b2 = SN[j * BB + i] * TC_INV;
    float m1 = blockReduceMax(fmaxf(a1, a2), red);
    float s1 = blockReduceSum(expf(a1 - m1) + expf(a2 - m1), red);
    float m2 = blockReduceMax(fmaxf(b1, b2), red);
    float s2 = blockReduceSum(expf(b1 - m2) + expf(b2 - m2), red);
    if (j == 0) {
        float diag = SP[i * BB + i] * TC_INV;
        l1[i] = logf(s1) + m1 - diag;
        l2[i] = logf(s2) + m2 - diag;
    }
}

// ---------------- weighted pairwise-distance matrix E ----------------
// block per i, 256 threads (thread = j)
__global__ void dist_kernel(const float* __restrict__ ind, const float* __restrict__ ivn,
                            const float* __restrict__ faT, const float* __restrict__ ivnT,
                            float* __restrict__ E) {
    int i = blockIdx.x, j = threadIdx.x;
    __shared__ float ind_s[CD], ivn_s[CD];
    for (int c = j; c < CD; c += 256) { ind_s[c] = ind[i * CD + c]; ivn_s[c] = ivn[i * CD + c]; }
    __syncthreads();
    float d = 0.f, vv = 0.f;
    for (int c = 0; c < CD; c++) {
        float t = ind_s[c] - faT[c * BB + j] + 1e-6f;
        d = fmaf(t, t, d);
        vv = fmaf(ivn_s[c], ivnT[c * BB + j], vv);
    }
    E[i * BB + j] = (i == j) ? d : d * vv * (1.f / 255.f);
}

// ---------------- final scalar losses ----------------
__global__ void final_kernel(const float* __restrict__ E, const float* __restrict__ l1,
                             const float* __restrict__ l2, float* __restrict__ out) {
    int t = threadIdx.x;   // 256
    __shared__ float red[8];
    float r = 0.f, c = 0.f;
    for (int j = 0; j < BB; j++) r += E[t * BB + j];
    for (int i2 = 0; i2 < BB; i2++) c += E[i2 * BB + t];
    float a3 = fmaxf(r + 0.6f, 0.f);
    float a4 = fmaxf(c + 0.6f, 0.f);
    float s3 = blockReduceSum(a3, red);
    float s4 = blockReduceSum(a4, red);
    float s1 = blockReduceSum(l1[t], red);
    float s2 = blockReduceSum(l2[t], red);
    if (t == 0) {
        out[0] = (s1 + s2) * (0.5f / (float)BB);
        out[1] = (s3 + s4) * (0.5f / (float)BB);
    }
}

// ---------------- launch ----------------
extern "C" void kernel_launch(void* const* d_in, const int* in_sizes, int n_in,
                              void* d_out, int out_size) {
    const float* ev   = (const float*)d_in[0];
    const float* ea   = (const float*)d_in[1];
    const int*   masks= (const int*)  d_in[2];
    const float* Wfc1 = (const float*)d_in[3];
    const float* Wfc2 = (const float*)d_in[4];
    const float* Wc1  = (const float*)d_in[5];
    const float* Wc2  = (const float*)d_in[6];
    float* out = (float*)d_out;

    float *hfc, *fa, *faT, *h1, *fv, *ind, *ivn, *ivnT, *invrho, *Sij, *SP, *SN, *E, *l1, *l2;
    cudaGetSymbolAddress((void**)&hfc,    d_hfc);
    cudaGetSymbolAddress((void**)&fa,     d_fa);
    cudaGetSymbolAddress((void**)&faT,    d_faT);
    cudaGetSymbolAddress((void**)&h1,     d_h1);
    cudaGetSymbolAddress((void**)&fv,     d_fv);
    cudaGetSymbolAddress((void**)&ind,    d_ind);
    cudaGetSymbolAddress((void**)&ivn,    d_ivn);
    cudaGetSymbolAddress((void**)&ivnT,   d_ivnT);
    cudaGetSymbolAddress((void**)&invrho, d_invrho);
    cudaGetSymbolAddress((void**)&Sij,    d_Sij);
    cudaGetSymbolAddress((void**)&SP,     d_SP);
    cudaGetSymbolAddress((void**)&SN,     d_SN);
    cudaGetSymbolAddress((void**)&E,      d_E);
    cudaGetSymbolAddress((void**)&l1,     d_l1);
    cudaGetSymbolAddress((void**)&l2,     d_l2);

    // audio branch
    gemm_nt<<<dim3(CD / 16, BB / 16), dim3(16, 16)>>>(ea, Wfc1, hfc, 2048, CD, 1);
    gemm_nt<<<dim3(CD / 16, BB / 16), dim3(16, 16)>>>(hfc, Wfc2, fa, CD, CD, 0);
    transpose_fa<<<512, 256>>>(fa, faT);

    // visual branch
    conv3x3<384, true ><<<dim3(CD / 16, BB), 196>>>(ev, Wc1, h1);
    conv3x3<CD,  false><<<dim3(CD / 16, BB), 196>>>(h1, Wc2, fv);

    indvec_kernel<<<BB, 256>>>(fv, masks, ind);
    invrho_kernel<<<BB, HWD>>>(fv, invrho);
    ivn_kernel<<<BB, CD>>>(ind, ivn, ivnT);

    // similarity tensor + top-k soft pooling
    sij_gemm<<<dim3(4, 4, BB), dim3(16, 16)>>>(ivn, fv, invrho, Sij);
    topk_sp_sn<<<dim3(BB, BB), 256>>>(Sij, SP, SN);

    // losses
    loss12_kernel<<<BB, 256>>>(SP, SN, l1, l2);
    dist_kernel<<<BB, 256>>>(ind, ivn, faT, ivnT, E);
    final_kernel<<<1, 256>>>(E, l1, l2, out);
}

// round 3
// speedup vs baseline: 2.5507x; 2.5507x over previous
#include <cuda_runtime.h>
#include <math.h>
#include <stdint.h>

// ---------------- problem constants ----------------
#define BB 256
#define HWD 196      // 14*14
#define CD 512
#define TS_INV (1.0f/0.03f)
#define TC_INV (1.0f/0.07f)

// ---------------- scratch (device globals; no runtime allocation) ----------------
__device__ float d_hfc[BB*CD];
__device__ float d_fa[BB*CD];
__device__ float d_faT[CD*BB];
__device__ float d_h1[BB*CD*HWD];     // relu(conv1) 102.8 MB
__device__ float d_fv[BB*CD*HWD];     // conv2 output 102.8 MB
__device__ float d_ind[BB*CD];
__device__ float d_ivn[BB*CD];
__device__ float d_ivnT[CD*BB];
__device__ float d_invrho[BB*HWD];
__device__ float d_Sij[BB*BB*HWD];    // 51.4 MB
__device__ float d_SP[BB*BB];
__device__ float d_SN[BB*BB];
__device__ float d_E[BB*BB];
__device__ float d_l1[BB];
__device__ float d_l2[BB];
__device__ float d_wT1[9*512*384];    // conv1 weights [t][oc][ic]
__device__ float d_wT2[9*512*512];    // conv2 weights [t][oc][ic]

// ---------------- reduction helpers ----------------
__device__ __forceinline__ float warpReduceSum(float v) {
#pragma unroll
    for (int o = 16; o > 0; o >>= 1) v += __shfl_xor_sync(0xffffffffu, v, o);
    return v;
}
__device__ __forceinline__ float warpReduceMax(float v) {
#pragma unroll
    for (int o = 16; o > 0; o >>= 1) v = fmaxf(v, __shfl_xor_sync(0xffffffffu, v, o));
    return v;
}
__device__ __forceinline__ float blockReduceSum(float v, float* red) {
    __syncthreads();
    int lane = threadIdx.x & 31, wid = threadIdx.x >> 5;
    v = warpReduceSum(v);
    if (lane == 0) red[wid] = v;
    __syncthreads();
    int nw = (blockDim.x + 31) >> 5;
    if (wid == 0) {
        float r = (threadIdx.x < nw) ? red[threadIdx.x] : 0.f;
        r = warpReduceSum(r);
        if (lane == 0) red[0] = r;
    }
    __syncthreads();
    return red[0];
}
__device__ __forceinline__ float blockReduceMax(float v, float* red) {
    __syncthreads();
    int lane = threadIdx.x & 31, wid = threadIdx.x >> 5;
    v = warpReduceMax(v);
    if (lane == 0) red[wid] = v;
    __syncthreads();
    int nw = (blockDim.x + 31) >> 5;
    if (wid == 0) {
        float r = (threadIdx.x < nw) ? red[threadIdx.x] : -INFINITY;
        r = warpReduceMax(r);
        if (lane == 0) red[0] = r;
    }
    __syncthreads();
    return red[0];
}

__device__ __forceinline__ float sigmoidf_stable(float x) {
    if (x >= 0.f) { float e = expf(-x); return 1.f / (1.f + e); }
    float e = expf(x); return e / (1.f + e);
}

// ---------------- bf16 split helpers ----------------
__device__ __forceinline__ uint32_t pack2bf(float e0, float e1) {
    // reg.lo = bf16(e0), reg.hi = bf16(e1)
    uint32_t r;
    asm("cvt.rn.bf16x2.f32 %0, %1, %2;" : "=r"(r) : "f"(e1), "f"(e0));
    return r;
}
__device__ __forceinline__ float bfx2_lo_f(uint32_t p) { return __uint_as_float(p << 16); }
__device__ __forceinline__ float bfx2_hi_f(uint32_t p) { return __uint_as_float(p & 0xffff0000u); }

__device__ __forceinline__ void mma_bf16(float c[4], const uint32_t a[4], uint32_t b0, uint32_t b1) {
    asm volatile(
        "mma.sync.aligned.m16n8k16.row.col.f32.bf16.bf16.f32 "
        "{%0,%1,%2,%3}, {%4,%5,%6,%7}, {%8,%9}, {%0,%1,%2,%3};"
        : "+f"(c[0]), "+f"(c[1]), "+f"(c[2]), "+f"(c[3])
        : "r"(a[0]), "r"(a[1]), "r"(a[2]), "r"(a[3]), "r"(b0), "r"(b1));
}

// ---------------- weight transpose: w[oc][ic][t] -> wT[t][oc][ic] ----------------
__global__ void transposeW(const float* __restrict__ w, float* __restrict__ wT, int IC) {
    int idx = blockIdx.x * 256 + threadIdx.x;
    if (idx >= 512 * IC * 9) return;
    int oc = idx / (IC * 9);
    int r  = idx % (IC * 9);
    int ic = r / 9;
    int t  = r % 9;
    wT[((size_t)t * 512 + oc) * IC + ic] = w[idx];
}

// ---------------- GEMM: C[m,n] = sum_k A[m,k] * W[n,k], optional relu ----------------
__global__ void gemm_nt(const float* __restrict__ A, const float* __restrict__ W,
                        float* __restrict__ C, int K, int N, int relu) {
    __shared__ float As[16][17], Ws[16][17];
    int tx = threadIdx.x, ty = threadIdx.y;
    int m = blockIdx.y * 16 + ty;
    int n0 = blockIdx.x * 16;
    float acc = 0.f;
    for (int k0 = 0; k0 < K; k0 += 16) {
        As[ty][tx] = A[m * K + k0 + tx];
        Ws[ty][tx] = W[(n0 + ty) * K + k0 + tx];
        __syncthreads();
#pragma unroll
        for (int kk = 0; kk < 16; kk++) acc = fmaf(As[ty][kk], Ws[tx][kk], acc);
        __syncthreads();
    }
    C[m * N + n0 + tx] = relu ? fmaxf(acc, 0.f) : acc;
}

// ---------------- 3x3 SAME conv via implicit GEMM on tensor cores ----------------
// grid (OC/64, B), block 256 (8 warps = 4 oc-groups x 2 pos-halves)
// per warp: 16 oc x 104 positions, K = IC*9 via (ic-chunk=32, 9 taps, kstep=16)
// bf16 hi/lo split: 3 MMAs per k-step for ~fp32 accuracy.
template<int IC, bool RELU>
__global__ void __launch_bounds__(256, 2) conv3x3_mma(const float* __restrict__ in,
                                                      const float* __restrict__ wT,
                                                      float* __restrict__ out) {
    __shared__ float plane[32][292];   // per-ic 18x16 padded cells (+4 pad)
    __shared__ float wsh[32][65];      // [ic within chunk][oc within 64] (+1 pad)

    const int b = blockIdx.y;
    const int oc0 = blockIdx.x * 64;
    const int tid = threadIdx.x;
    const int warp = tid >> 5, lane = tid & 31;
    const int gid = lane >> 2, tig = lane & 3;
    const int oc_w = (warp >> 1) * 16;
    const int pos_off = (warp & 1) * 104;

    // zero full plane (halo + overflow cells stay zero forever)
    for (int e = tid; e < 32 * 292; e += 256) ((float*)plane)[e] = 0.f;

    // per-lane base coordinates (center cell) for the 13 n-tiles (n index = gid)
    int base[13];
#pragma unroll
    for (int pt = 0; pt < 13; pt++) {
        int p = pos_off + pt * 8 + gid;
        base[pt] = (p < HWD) ? ((p / 14) + 1) * 16 + (p % 14) + 1 : 273; // 273-17 >= 256 -> zeros
    }

    float C[13][4];
#pragma unroll
    for (int pt = 0; pt < 13; pt++) {
#pragma unroll
        for (int r = 0; r < 4; r++) C[pt][r] = 0.f;
    }

    const float* inb = in + (size_t)b * IC * HWD;

    for (int ic0 = 0; ic0 < IC; ic0 += 32) {
        __syncthreads();   // previous chunk's compute done before plane overwrite
        for (int e = tid; e < 32 * HWD; e += 256) {
            int i = e / HWD, p = e % HWD;
            plane[i][((p / 14) + 1) * 16 + (p % 14) + 1] = inb[(ic0 + i) * HWD + p];
        }
        for (int t = 0; t < 9; t++) {
            __syncthreads();  // plane ready (t=0) / previous tap's compute done
            for (int e = tid; e < 2048; e += 256) {
                int i = e & 31, o = e >> 5;
                wsh[i][o] = wT[((size_t)(t * 512 + oc0 + o)) * IC + ic0 + i];
            }
            __syncthreads();  // wsh ready
            // SAME conv: tap (dy,dx) reads in(y+dy-1, x+dx-1) -> offset (dy-1)*16 + (dx-1)
            const int toff = (t / 3 - 1) * 16 + (t % 3 - 1);
#pragma unroll
            for (int ks = 0; ks < 2; ks++) {
                const int k0 = ks * 16;
                // A fragments (weights), hi/lo split
                float w0 = wsh[k0 + 2 * tig    ][oc_w + gid];
                float w1 = wsh[k0 + 2 * tig + 1][oc_w + gid];
                float w2 = wsh[k0 + 2 * tig    ][oc_w + gid + 8];
                float w3 = wsh[k0 + 2 * tig + 1][oc_w + gid + 8];
                float w4 = wsh[k0 + 2 * tig + 8][oc_w + gid];
                float w5 = wsh[k0 + 2 * tig + 9][oc_w + gid];
                float w6 = wsh[k0 + 2 * tig + 8][oc_w + gid + 8];
                float w7 = wsh[k0 + 2 * tig + 9][oc_w + gid + 8];
                uint32_t ahi[4], alo[4];
                ahi[0] = pack2bf(w0, w1);
                ahi[1] = pack2bf(w2, w3);
                ahi[2] = pack2bf(w4, w5);
                ahi[3] = pack2bf(w6, w7);
                alo[0] = pack2bf(w0 - bfx2_lo_f(ahi[0]), w1 - bfx2_hi_f(ahi[0]));
                alo[1] = pack2bf(w2 - bfx2_lo_f(ahi[1]), w3 - bfx2_hi_f(ahi[1]));
                alo[2] = pack2bf(w4 - bfx2_lo_f(ahi[2]), w5 - bfx2_hi_f(ahi[2]));
                alo[3] = pack2bf(w6 - bfx2_lo_f(ahi[3]), w7 - bfx2_hi_f(ahi[3]));
#pragma unroll
                for (int pt = 0; pt < 13; pt++) {
                    const int pc = base[pt] + toff;
                    float f0 = plane[k0 + 2 * tig    ][pc];
                    float f1 = plane[k0 + 2 * tig + 1][pc];
                    float f2 = plane[k0 + 2 * tig + 8][pc];
                    float f3 = plane[k0 + 2 * tig + 9][pc];
                    uint32_t b0h = pack2bf(f0, f1);
                    uint32_t b1h = pack2bf(f2, f3);
                    uint32_t b0l = pack2bf(f0 - bfx2_lo_f(b0h), f1 - bfx2_hi_f(b0h));
                    uint32_t b1l = pack2bf(f2 - bfx2_lo_f(b1h), f3 - bfx2_hi_f(b1h));
                    mma_bf16(C[pt], ahi, b0h, b1h);
                    mma_bf16(C[pt], alo, b0h, b1h);
                    mma_bf16(C[pt], ahi, b0l, b1l);
                }
            }
        }
    }

    // store: C rows = oc (gid, gid+8), cols = pos (tig*2, tig*2+1)
    float* ob = out + ((size_t)b * CD + oc0 + oc_w) * HWD;
#pragma unroll
    for (int pt = 0; pt < 13; pt++) {
        int p = pos_off + pt * 8 + tig * 2;
        if (p < HWD) {
            float v0 = C[pt][0], v2 = C[pt][2];
            if (RELU) { v0 = fmaxf(v0, 0.f); v2 = fmaxf(v2, 0.f); }
            ob[gid * HWD + p] = v0;
            ob[(gid + 8) * HWD + p] = v2;
        }
        if (p + 1 < HWD) {
            float v1 = C[pt][1], v3 = C[pt][3];
            if (RELU) { v1 = fmaxf(v1, 0.f); v3 = fmaxf(v3, 0.f); }
            ob[gid * HWD + p + 1] = v1;
            ob[(gid + 8) * HWD + p + 1] = v3;
        }
    }
}

// ---------------- masked mean pooling -> ind_vec ----------------
__global__ void indvec_kernel(const float* __restrict__ fv, const int* __restrict__ masks,
                              float* __restrict__ ind) {
    int b = blockIdx.x;
    int tid = threadIdx.x;
    __shared__ float m_s[HWD];
    __shared__ float red[8];
    float mv = 0.f;
    if (tid < HWD) { mv = (float)masks[b * HWD + tid]; m_s[tid] = mv; }
    float tot = blockReduceSum(mv, red);
    float inv_m = 1.f / tot;
    int lane = tid & 31, wid = tid >> 5;
    for (int c = wid; c < CD; c += 8) {
        const float* rowp = fv + ((size_t)b * CD + c) * HWD;
        float s = 0.f;
        for (int p = lane; p < HWD; p += 32) s += rowp[p] * m_s[p];
        s = warpReduceSum(s);
        if (lane == 0) ind[b * CD + c] = s * inv_m;
    }
}

// ---------------- per (b,p) inverse channel L2 norm ----------------
__global__ void invrho_kernel(const float* __restrict__ fv, float* __restrict__ invrho) {
    int b = blockIdx.x;
    int p = threadIdx.x;
    const float* base = fv + (size_t)b * CD * HWD + p;
    float s = 0.f;
    for (int c = 0; c < CD; c++) { float v = base[c * HWD]; s = fmaf(v, v, s); }
    invrho[b * HWD + p] = 1.f / fmaxf(sqrtf(s), 1e-12f);
}

// ---------------- normalize ind_vec -> ivn (+ transposed copy) ----------------
__global__ void ivn_kernel(const float* __restrict__ ind, float* __restrict__ ivn,
                           float* __restrict__ ivnT) {
    int b = blockIdx.x, c = threadIdx.x;
    __shared__ float red[16];
    float v = ind[b * CD + c];
    float ss = blockReduceSum(v * v, red);
    float o = v / fmaxf(sqrtf(ss), 1e-12f);
    ivn[b * CD + c] = o;
    ivnT[c * BB + b] = o;
}

// ---------------- transpose fa ----------------
__global__ void transpose_fa(const float* __restrict__ fa, float* __restrict__ faT) {
    int idx = blockIdx.x * 256 + threadIdx.x;
    int b = idx >> 9, c = idx & 511;
    faT[c * BB + b] = fa[idx];
}

// ---------------- Sij[i,j,p] = <ivn[j], fv[i,:,p]> * invrho[i,p] ----------------
__global__ void sij_gemm(const float* __restrict__ ivn, const float* __restrict__ fv,
                         const float* __restrict__ invrho, float* __restrict__ Sij) {
    int i = blockIdx.z;
    int p0 = blockIdx.x * 64;
    int j0 = blockIdx.y * 64;
    __shared__ float As[64][17];
    __shared__ float Bs[16][65];
    int tid = threadIdx.y * 16 + threadIdx.x;
    float acc[4][4] = {};
    const float* fvi = fv + (size_t)i * CD * HWD;
    for (int k0 = 0; k0 < CD; k0 += 16) {
#pragma unroll
        for (int r = 0; r < 4; r++) {
            int e = tid + r * 256;
            int row = e >> 4, col = e & 15;
            As[row][col] = ivn[(j0 + row) * CD + k0 + col];
        }
#pragma unroll
        for (int r = 0; r < 4; r++) {
            int e = tid + r * 256;
            int row = e >> 6, col = e & 63;
            int p = p0 + col;
            Bs[row][col] = (p < HWD) ? fvi[(k0 + row) * HWD + p] : 0.f;
        }
        __syncthreads();
#pragma unroll
        for (int kk = 0; kk < 16; kk++) {
            float a[4], bb[4];
#pragma unroll
            for (int r = 0; r < 4; r++) a[r] = As[threadIdx.y * 4 + r][kk];
#pragma unroll
            for (int c = 0; c < 4; c++) bb[c] = Bs[kk][threadIdx.x * 4 + c];
#pragma unroll
            for (int r = 0; r < 4; r++)
#pragma unroll
                for (int c = 0; c < 4; c++)
                    acc[r][c] = fmaf(a[r], bb[c], acc[r][c]);
        }
        __syncthreads();
    }
#pragma unroll
    for (int r = 0; r < 4; r++) {
        int j = j0 + threadIdx.y * 4 + r;
#pragma unroll
        for (int c = 0; c < 4; c++) {
            int p = p0 + threadIdx.x * 4 + c;
            if (p < HWD)
                Sij[((size_t)(i * BB + j)) * HWD + p] = acc[r][c] * invrho[i * HWD + p];
        }
    }
}

// ---------------- exact top-k thresholds via bitonic sort + soft-mask pooling ----------------
__global__ void topk_sp_sn(const float* __restrict__ Sij, float* __restrict__ SP,
                           float* __restrict__ SN) {
    int i = blockIdx.y, j = blockIdx.x;
    int tid = threadIdx.x;
    __shared__ float sm[256];
    __shared__ float red[8];
    const float* row = Sij + ((size_t)(i * BB + j)) * HWD;
    sm[tid] = (tid < HWD) ? row[tid] : -INFINITY;
    __syncthreads();
    for (int k = 2; k <= 256; k <<= 1) {
        for (int s = k >> 1; s > 0; s >>= 1) {
            int ixj = tid ^ s;
            if (ixj > tid) {
                float a = sm[tid], b2 = sm[ixj];
                bool up = ((tid & k) == 0);
                if ((a > b2) == up) { sm[tid] = b2; sm[ixj] = a; }
            }
            __syncthreads();
        }
    }
    float pos_thr = sm[237];
    float neg_thr = sm[157];
    float val = (tid >= 60) ? sm[tid] : 0.f;
    float mp = 0.f, mn = 0.f;
    if (tid >= 60) {
        mp = sigmoidf_stable((val - pos_thr) * TS_INV);
        mn = 1.f - sigmoidf_stable((val - neg_thr) * TS_INV);
    }
    float s_vp = blockReduceSum(val * mp, red);
    float s_p  = blockReduceSum(mp, red);
    float s_vn = blockReduceSum(val * mn, red);
    float s_n  = blockReduceSum(mn, red);
    if (tid == 0) {
        SP[i * BB + j] = s_vp / s_p;
        SN[i * BB + j] = s_vn / s_n;
    }
}

// ---------------- contrastive losses ----------------
__global__ void loss12_kernel(const float* __restrict__ SP, const float* __restrict__ SN,
                              float* __restrict__ l1, float* __restrict__ l2) {
    int i = blockIdx.x, j = threadIdx.x;
    __shared__ float red[8];
    float a1 = SP[i * BB + j] * TC_INV, a2 = SN[i * BB + j] * TC_INV;
    float b1 = SP[j * BB + i] * TC_INV, b2 = SN[j * BB + i] * TC_INV;
    float m1 = blockReduceMax(fmaxf(a1, a2), red);
    float s1 = blockReduceSum(expf(a1 - m1) + expf(a2 - m1), red);
    float m2 = blockReduceMax(fmaxf(b1, b2), red);
    float s2 = blockReduceSum(expf(b1 - m2) + expf(b2 - m2), red);
    if (j == 0) {
        float diag = SP[i * BB + i] * TC_INV;
        l1[i] = logf(s1) + m1 - diag;
        l2[i] = logf(s2) + m2 - diag;
    }
}

// ---------------- weighted pairwise-distance matrix E ----------------
__global__ void dist_kernel(const float* __restrict__ ind, const float* __restrict__ ivn,
                            const float* __restrict__ faT, const float* __restrict__ ivnT,
                            float* __restrict__ E) {
    int i = blockIdx.x, j = threadIdx.x;
    __shared__ float ind_s[CD], ivn_s[CD];
    for (int c = j; c < CD; c += 256) { ind_s[c] = ind[i * CD + c]; ivn_s[c] = ivn[i * CD + c]; }
    __syncthreads();
    float d = 0.f, vv = 0.f;
    for (int c = 0; c < CD; c++) {
        float t = ind_s[c] - faT[c * BB + j] + 1e-6f;
        d = fmaf(t, t, d);
        vv = fmaf(ivn_s[c], ivnT[c * BB + j], vv);
    }
    E[i * BB + j] = (i == j) ? d : d * vv * (1.f / 255.f);
}

// ---------------- final scalar losses ----------------
__global__ void final_kernel(const float* __restrict__ E, const float* __restrict__ l1,
                             const float* __restrict__ l2, float* __restrict__ out) {
    int t = threadIdx.x;   // 256
    __shared__ float red[8];
    float r = 0.f, c = 0.f;
    for (int j = 0; j < BB; j++) r += E[t * BB + j];
    for (int i2 = 0; i2 < BB; i2++) c += E[i2 * BB + t];
    float a3 = fmaxf(r + 0.6f, 0.f);
    float a4 = fmaxf(c + 0.6f, 0.f);
    float s3 = blockReduceSum(a3, red);
    float s4 = blockReduceSum(a4, red);
    float s1 = blockReduceSum(l1[t], red);
    float s2 = blockReduceSum(l2[t], red);
    if (t == 0) {
        out[0] = (s1 + s2) * (0.5f / (float)BB);
        out[1] = (s3 + s4) * (0.5f / (float)BB);
    }
}

// ---------------- launch ----------------
extern "C" void kernel_launch(void* const* d_in, const int* in_sizes, int n_in,
                              void* d_out, int out_size) {
    const float* ev   = (const float*)d_in[0];
    const float* ea   = (const float*)d_in[1];
    const int*   masks= (const int*)  d_in[2];
    const float* Wfc1 = (const float*)d_in[3];
    const float* Wfc2 = (const float*)d_in[4];
    const float* Wc1  = (const float*)d_in[5];
    const float* Wc2  = (const float*)d_in[6];
    float* out = (float*)d_out;

    float *hfc, *fa, *faT, *h1, *fv, *ind, *ivn, *ivnT, *invrho, *Sij, *SP, *SN, *E, *l1, *l2;
    float *wT1, *wT2;
    cudaGetSymbolAddress((void**)&hfc,    d_hfc);
    cudaGetSymbolAddress((void**)&fa,     d_fa);
    cudaGetSymbolAddress((void**)&faT,    d_faT);
    cudaGetSymbolAddress((void**)&h1,     d_h1);
    cudaGetSymbolAddress((void**)&fv,     d_fv);
    cudaGetSymbolAddress((void**)&ind,    d_ind);
    cudaGetSymbolAddress((void**)&ivn,    d_ivn);
    cudaGetSymbolAddress((void**)&ivnT,   d_ivnT);
    cudaGetSymbolAddress((void**)&invrho, d_invrho);
    cudaGetSymbolAddress((void**)&Sij,    d_Sij);
    cudaGetSymbolAddress((void**)&SP,     d_SP);
    cudaGetSymbolAddress((void**)&SN,     d_SN);
    cudaGetSymbolAddress((void**)&E,      d_E);
    cudaGetSymbolAddress((void**)&l1,     d_l1);
    cudaGetSymbolAddress((void**)&l2,     d_l2);
    cudaGetSymbolAddress((void**)&wT1,    d_wT1);
    cudaGetSymbolAddress((void**)&wT2,    d_wT2);

    // audio branch
    gemm_nt<<<dim3(CD / 16, BB / 16), dim3(16, 16)>>>(ea, Wfc1, hfc, 2048, CD, 1);
    gemm_nt<<<dim3(CD / 16, BB / 16), dim3(16, 16)>>>(hfc, Wfc2, fa, CD, CD, 0);
    transpose_fa<<<512, 256>>>(fa, faT);

    // weight layouts for implicit-GEMM convs
    transposeW<<<(512 * 384 * 9 + 255) / 256, 256>>>(Wc1, wT1, 384);
    transposeW<<<(512 * 512 * 9 + 255) / 256, 256>>>(Wc2, wT2, 512);

    // visual branch (tensor-core convs)
    conv3x3_mma<384, true ><<<dim3(CD / 64, BB), 256>>>(ev, wT1, h1);
    conv3x3_mma<512, false><<<dim3(CD / 64, BB), 256>>>(h1, wT2, fv);

    indvec_kernel<<<BB, 256>>>(fv, masks, ind);
    invrho_kernel<<<BB, HWD>>>(fv, invrho);
    ivn_kernel<<<BB, CD>>>(ind, ivn, ivnT);

    // similarity tensor + top-k soft pooling
    sij_gemm<<<dim3(4, 4, BB), dim3(16, 16)>>>(ivn, fv, invrho, Sij);
    topk_sp_sn<<<dim3(BB, BB), 256>>>(Sij, SP, SN);

    // losses
    loss12_kernel<<<BB, 256>>>(SP, SN, l1, l2);
    dist_kernel<<<BB, 256>>>(ind, ivn, faT, ivnT, E);
    final_kernel<<<1, 256>>>(E, l1, l2, out);
}